// round 6
// baseline (speedup 1.0000x reference)
#include <cuda_runtime.h>
#include <math.h>

#define NN 50000
#define NE 400000
#define HID 128
#define MUL1 64
#define FEAT 320
#define TE 64          // edges per tile: 32 pairs, lane cg owns pair cg
#define TN 64          // nodes per tile in node phase
#define NTHREADS 512
#define NBLOCKS 148

typedef unsigned long long u64;

__device__ __forceinline__ u64 pack2(float a, float b) {
    u64 r; asm("mov.b64 %0, {%1,%2};" : "=l"(r) : "f"(a), "f"(b)); return r;
}
__device__ __forceinline__ void unpack2(u64 v, float& a, float& b) {
    asm("mov.b64 {%0,%1}, %2;" : "=f"(a), "=f"(b) : "l"(v));
}
__device__ __forceinline__ void fma2(u64& d, u64 a, u64 b) {
    asm("fma.rn.f32x2 %0, %1, %2, %0;" : "+l"(d) : "l"(a), "l"(b));
}
__device__ __forceinline__ void red4(float* p, float a, float b, float c, float d) {
    asm volatile("red.global.add.v4.f32 [%0], {%1,%2,%3,%4};"
                 :: "l"(p), "f"(a), "f"(b), "f"(c), "f"(d) : "memory");
}
__device__ __forceinline__ void red2(float* p, float a, float b) {
    asm volatile("red.global.add.v2.f32 [%0], {%1,%2};"
                 :: "l"(p), "f"(a), "f"(b) : "memory");
}

// 64 MB scratch accumulator. Zero at module load; node phase re-zeroes every
// element it consumes, restoring the invariant for the next graph replay.
__device__ float g_A[(size_t)NN * FEAT];
__device__ unsigned int g_arrive;
__device__ unsigned int g_depart;

// smem float offsets (edge phase)
#define OWC   0        // Wcs [128][192]   24576 (Wtp0|Wtp1 raw)
#define OW2   24576    // W2s [64][128]    8192  (raw)
#define ORAD  32768    // radS [64][9]     576   (pad 9: conflict-free)
#define OY1   33344    // y1S [64][4]      256
#define OIDX  33600    // snd[64], rcv[64] 128
#define OH2   33728    // h2f [64j][64e]   4096
#define ONF   37824    // nf2f [128k][64e] 8192
#define OES   33728    // eS [64][193] overlay on h2f+nf2f  12352
#define SMEM_FLOATS 46144
#define SMEM_BYTES (SMEM_FLOATS * 4)   // 184,576 B
// node overlay: Wm [192][128] @0 (24576), b2f [32][192][2] @24576 (12288)

__global__ void __launch_bounds__(NTHREADS, 1)
ace_fused_kernel(const float* __restrict__ node_attrs,
                 const int* __restrict__ edge_index,
                 const float* __restrict__ edge_vec,
                 const float* __restrict__ edge_len,
                 const float* __restrict__ W1,
                 const float* __restrict__ W2,
                 const float* __restrict__ Wtp0,
                 const float* __restrict__ Wtp1,
                 const float* __restrict__ Wmix0,
                 float* __restrict__ out) {
    extern __shared__ float smem[];
    float* Wcs  = smem + OWC;
    float* W2s  = smem + OW2;
    float* radS = smem + ORAD;
    float* y1S  = smem + OY1;
    int*   sndS = (int*)(smem + OIDX);
    int*   rcvS = sndS + TE;
    float* h2f  = smem + OH2;
    float* nf2f = smem + ONF;
    float* eS   = smem + OES;

    const int tid = threadIdx.x;
    const int cg = tid & 31;       // lane: owns edge-pair cg (edges 2cg, 2cg+1)
    const int eg = tid >> 5;       // warp 0..15: owns column slices

    // stage weights raw (scales folded into silu-output constant)
    for (int i = tid; i < 128 * 192; i += NTHREADS) {
        int k = i / 192, c = i % 192;
        Wcs[i] = (c < 128) ? Wtp0[k * 128 + c] : Wtp1[k * 64 + (c - 128)];
    }
    for (int i = tid; i < 64 * 128; i += NTHREADS) W2s[i] = W2[i];
    __syncthreads();

    // ================= EDGE PHASE =================
    const int ntiles = NE / TE;  // 6250 exact
    for (int tile = blockIdx.x; tile < ntiles; tile += gridDim.x) {
        const int ebase = tile * TE;

        // ---- Phase A: per-edge scalars ----
        if (tid < TE) {
            int e = ebase + tid;
            float x = edge_len[e];
            bool valid = (x > 0.f) && (x < 5.0f);
            // sqrt(2/5)/x * 1/sqrt(8)  (W1 scale folded into silu argument)
            float pref = valid ? (0.22360679774997896f / x) : 0.f;
#pragma unroll
            for (int r = 0; r < 8; r++)
                radS[tid * 9 + r] = pref * sinf((float)(r + 1) * 0.6283185307179586f * x);
            float vx = edge_vec[e * 3 + 0];
            float vy = edge_vec[e * 3 + 1];
            float vz = edge_vec[e * 3 + 2];
            float rn = rsqrtf(vx * vx + vy * vy + vz * vz) * 1.7320508075688772f;
            y1S[tid * 4 + 0] = vy * rn;
            y1S[tid * 4 + 1] = vz * rn;
            y1S[tid * 4 + 2] = vx * rn;
            sndS[tid] = edge_index[e];
            rcvS[tid] = edge_index[NE + e];
        }
        __syncthreads();

        // ---- Phase B: h = const * silu(rad @ W1), layout h2f[j][e] ----
#pragma unroll
        for (int l = 0; l < (TE * 64) / NTHREADS; l++) {
            int idx = tid + l * NTHREADS;
            int j = idx >> 6, e = idx & 63;
            float s = 0.f;
#pragma unroll
            for (int r = 0; r < 8; r++)
                s += radS[e * 9 + r] * __ldg(&W1[r * 64 + j]);
            // 1.679177 * 0.125 * (1/sqrt(128))
            h2f[j * 64 + e] = 0.018552463f * s / (1.f + expf(-s));
        }
        __syncthreads();

        // ---- Phase C: R_n = h @ W2 (warp owns 8 cols), nf = attrs[snd]*R_n ----
        {
            u64 acc[8];
#pragma unroll
            for (int c = 0; c < 8; c++) acc[c] = 0ull;
            const float* wbase = &W2s[8 * eg];
#pragma unroll 4
            for (int j = 0; j < 64; j++) {
                u64 a2 = *(const u64*)&h2f[j * 64 + 2 * cg];      // pair-packed
                float4 w0 = *(const float4*)&wbase[j * 128];       // broadcast
                float4 w1 = *(const float4*)&wbase[j * 128 + 4];
                fma2(acc[0], a2, pack2(w0.x, w0.x));
                fma2(acc[1], a2, pack2(w0.y, w0.y));
                fma2(acc[2], a2, pack2(w0.z, w0.z));
                fma2(acc[3], a2, pack2(w0.w, w0.w));
                fma2(acc[4], a2, pack2(w1.x, w1.x));
                fma2(acc[5], a2, pack2(w1.y, w1.y));
                fma2(acc[6], a2, pack2(w1.z, w1.z));
                fma2(acc[7], a2, pack2(w1.w, w1.w));
            }
            int s0 = sndS[2 * cg], s1 = sndS[2 * cg + 1];
            float4 A00 = *(const float4*)&node_attrs[(u64)s0 * HID + 8 * eg];
            float4 A01 = *(const float4*)&node_attrs[(u64)s0 * HID + 8 * eg + 4];
            float4 A10 = *(const float4*)&node_attrs[(u64)s1 * HID + 8 * eg];
            float4 A11 = *(const float4*)&node_attrs[(u64)s1 * HID + 8 * eg + 4];
            float at0[8] = {A00.x, A00.y, A00.z, A00.w, A01.x, A01.y, A01.z, A01.w};
            float at1[8] = {A10.x, A10.y, A10.z, A10.w, A11.x, A11.y, A11.z, A11.w};
#pragma unroll
            for (int i = 0; i < 8; i++) {
                float r0v, r1v;
                unpack2(acc[i], r0v, r1v);
                // nf2f[k][pair] packed, lanes contiguous
                *(float2*)&nf2f[(8 * eg + i) * 64 + 2 * cg] =
                    make_float2(r0v * at0[i], r1v * at1[i]);
            }
        }
        __syncthreads();

        // ---- Phase D: [f0|t1] = nf @ Wcat (warp owns 12 cols) ----
        u64 acc[12];
#pragma unroll
        for (int c = 0; c < 12; c++) acc[c] = 0ull;
        {
            const float* wbase = &Wcs[12 * eg];
#pragma unroll 2
            for (int k = 0; k < 128; k++) {
                u64 a2 = *(const u64*)&nf2f[k * 64 + 2 * cg];     // pair-packed
                float4 w0 = *(const float4*)&wbase[k * 192];       // broadcast
                float4 w1 = *(const float4*)&wbase[k * 192 + 4];
                float4 w2 = *(const float4*)&wbase[k * 192 + 8];
                fma2(acc[0],  a2, pack2(w0.x, w0.x));
                fma2(acc[1],  a2, pack2(w0.y, w0.y));
                fma2(acc[2],  a2, pack2(w0.z, w0.z));
                fma2(acc[3],  a2, pack2(w0.w, w0.w));
                fma2(acc[4],  a2, pack2(w1.x, w1.x));
                fma2(acc[5],  a2, pack2(w1.y, w1.y));
                fma2(acc[6],  a2, pack2(w1.z, w1.z));
                fma2(acc[7],  a2, pack2(w1.w, w1.w));
                fma2(acc[8],  a2, pack2(w2.x, w2.x));
                fma2(acc[9],  a2, pack2(w2.y, w2.y));
                fma2(acc[10], a2, pack2(w2.z, w2.z));
                fma2(acc[11], a2, pack2(w2.w, w2.w));
            }
        }
        __syncthreads();   // all warps done reading nf2f/h2f before eS overlay

        // ---- stage to eS[edge][193] for coalesced scatter ----
#pragma unroll
        for (int i = 0; i < 12; i++) {
            int col = 12 * eg + i;
            float v0, v1;
            unpack2(acc[i], v0, v1);
            eS[(2 * cg) * 193 + col]     = v0;
            eS[(2 * cg + 1) * 193 + col] = v1;
        }
        __syncthreads();

        // ---- Phase E: coalesced vectorized scatter-add into g_A ----
#pragma unroll
        for (int p = 0; p < 2; p++) {
            int pr = eg * 2 + p;           // pair 0..31
            int el0 = 2 * pr, el1 = el0 + 1;
            int r0 = rcvS[el0], r1 = rcvS[el1];
            const float* e0 = &eS[el0 * 193];
            const float* e1 = &eS[el1 * 193];

            // f0: warp-uniform row, lane-contiguous cols
            red4(&g_A[(u64)r0 * FEAT + 4 * cg],
                 e0[4 * cg], e0[4 * cg + 1], e0[4 * cg + 2], e0[4 * cg + 3]);
            red4(&g_A[(u64)r1 * FEAT + 4 * cg],
                 e1[4 * cg], e1[4 * cg + 1], e1[4 * cg + 2], e1[4 * cg + 3]);

            // t1: m = 2cg, 2cg+1 -> 6 contiguous floats
            float u0a = e0[128 + 2 * cg], u1a = e0[128 + 2 * cg + 1];
            float u0b = e1[128 + 2 * cg], u1b = e1[128 + 2 * cg + 1];
            float ya0 = y1S[el0 * 4 + 0], ya1 = y1S[el0 * 4 + 1], ya2 = y1S[el0 * 4 + 2];
            float yb0 = y1S[el1 * 4 + 0], yb1 = y1S[el1 * 4 + 1], yb2 = y1S[el1 * 4 + 2];
            float* p0 = &g_A[(u64)r0 * FEAT + 128 + 6 * cg];
            float* p1 = &g_A[(u64)r1 * FEAT + 128 + 6 * cg];
            float va[6] = {u0a * ya0, u0a * ya1, u0a * ya2, u1a * ya0, u1a * ya1, u1a * ya2};
            float vb[6] = {u0b * yb0, u0b * yb1, u0b * yb2, u1b * yb0, u1b * yb1, u1b * yb2};
            if ((cg & 1) == 0) {
                red4(p0, va[0], va[1], va[2], va[3]);
                red2(p0 + 4, va[4], va[5]);
                red4(p1, vb[0], vb[1], vb[2], vb[3]);
                red2(p1 + 4, vb[4], vb[5]);
            } else {
                red2(p0, va[0], va[1]);
                red4(p0 + 2, va[2], va[3], va[4], va[5]);
                red2(p1, vb[0], vb[1]);
                red4(p1 + 2, vb[2], vb[3], vb[4], vb[5]);
            }
        }
        __syncthreads();
    }

    // ================= GRID BARRIER =================
    __threadfence();
    __syncthreads();
    if (tid == 0) {
        atomicAdd(&g_arrive, 1u);
        while (*(volatile unsigned int*)&g_arrive < (unsigned)gridDim.x)
            __nanosleep(128);
    }
    __syncthreads();
    __threadfence();

    // ================= NODE PHASE =================
    float* Wm  = smem;          // overlay
    float* b2f = smem + 24576;

    const float s_mix = 0.07216878364870323f;  // 1/sqrt(192)
    for (int i = tid; i < 192 * 128; i += NTHREADS) Wm[i] = Wmix0[i] * s_mix;
    __syncthreads();

    const int ntilesN = (NN + TN - 1) / TN;  // 782
    for (int tile = blockIdx.x; tile < ntilesN; tile += gridDim.x) {
        const int nbase = tile * TN;

        // ---- build B0 tile (reads g_A) ----
        for (int idx = tid; idx < TN * 192; idx += NTHREADS) {
            int e = idx / 192, k = idx % 192;
            int n = nbase + e;
            float v = 0.f;
            if (n < NN) {
                if (k < 128) {
                    float a = g_A[(u64)n * FEAT + k];
                    v = a * a;
                } else {
                    int m = k - 128;
                    const float* p = &g_A[(u64)n * FEAT + 128 + m * 3];
                    float q0 = p[0], q1 = p[1], q2 = p[2];
                    v = (q0 * q0 + q1 * q1 + q2 * q2) * 0.5773502691896258f;
                }
            }
            b2f[((e >> 1) * 192 + k) * 2 + (e & 1)] = v;
        }
        __syncthreads();

        // ---- copy A1 to out, zero scratch cols 128..319 ----
        for (int idx = tid; idx < TN * 192; idx += NTHREADS) {
            int e = idx / 192, k = idx % 192;
            int n = nbase + e;
            if (n < NN) {
                u64 off = (u64)n * FEAT + 128 + k;
                out[off] = g_A[off];
                g_A[off] = 0.f;
            }
        }

        // ---- mix0 = B0 @ Wmix0' (thread owns cols 4cg..4cg+3) ----
        u64 acc[2][4];
#pragma unroll
        for (int p = 0; p < 2; p++)
#pragma unroll
            for (int c = 0; c < 4; c++) acc[p][c] = 0ull;
#pragma unroll 2
        for (int k = 0; k < 192; k++) {
            u64 a[2];
#pragma unroll
            for (int p = 0; p < 2; p++)
                a[p] = *(const u64*)&b2f[((eg * 2 + p) * 192 + k) * 2];
            float4 w4 = *(const float4*)&Wm[k * 128 + 4 * cg];
            u64 wd0 = pack2(w4.x, w4.x);
            u64 wd1 = pack2(w4.y, w4.y);
            u64 wd2 = pack2(w4.z, w4.z);
            u64 wd3 = pack2(w4.w, w4.w);
#pragma unroll
            for (int p = 0; p < 2; p++) {
                fma2(acc[p][0], a[p], wd0);
                fma2(acc[p][1], a[p], wd1);
                fma2(acc[p][2], a[p], wd2);
                fma2(acc[p][3], a[p], wd3);
            }
        }

        // ---- out[:, :128] = A0 + mix0; zero scratch cols 0..127 ----
#pragma unroll
        for (int p = 0; p < 2; p++) {
            int n0 = nbase + (eg * 2 + p) * 2;
            int n1 = n0 + 1;
            float a0, b0, a1, b1, a2, b2, a3, b3;
            unpack2(acc[p][0], a0, b0);
            unpack2(acc[p][1], a1, b1);
            unpack2(acc[p][2], a2, b2);
            unpack2(acc[p][3], a3, b3);
            if (n0 < NN) {
                u64 off = (u64)n0 * FEAT + 4 * cg;
                float4 A0 = *(const float4*)&g_A[off];
                *(float4*)&out[off] = make_float4(A0.x + a0, A0.y + a1, A0.z + a2, A0.w + a3);
                *(float4*)&g_A[off] = make_float4(0.f, 0.f, 0.f, 0.f);
            }
            if (n1 < NN) {
                u64 off = (u64)n1 * FEAT + 4 * cg;
                float4 A0 = *(const float4*)&g_A[off];
                *(float4*)&out[off] = make_float4(A0.x + b0, A0.y + b1, A0.z + b2, A0.w + b3);
                *(float4*)&g_A[off] = make_float4(0.f, 0.f, 0.f, 0.f);
            }
        }
        __syncthreads();
    }

    // ---- reset barrier counters (last block out) ----
    __syncthreads();
    if (tid == 0) {
        __threadfence();
        unsigned d = atomicAdd(&g_depart, 1u);
        if (d == (unsigned)gridDim.x - 1) {
            g_arrive = 0;
            g_depart = 0;
            __threadfence();
        }
    }
}

extern "C" void kernel_launch(void* const* d_in, const int* in_sizes, int n_in,
                              void* d_out, int out_size) {
    const float* node_attrs = (const float*)d_in[0];
    const int*   edge_index = (const int*)d_in[1];
    const float* edge_vec   = (const float*)d_in[2];
    const float* edge_len   = (const float*)d_in[3];
    const float* W1         = (const float*)d_in[4];
    const float* W2         = (const float*)d_in[5];
    const float* Wtp0       = (const float*)d_in[6];
    const float* Wtp1       = (const float*)d_in[7];
    const float* Wmix0      = (const float*)d_in[8];
    float* out = (float*)d_out;

    cudaFuncSetAttribute(ace_fused_kernel, cudaFuncAttributeMaxDynamicSharedMemorySize, SMEM_BYTES);

    ace_fused_kernel<<<NBLOCKS, NTHREADS, SMEM_BYTES>>>(
        node_attrs, edge_index, edge_vec, edge_len, W1, W2, Wtp0, Wtp1, Wmix0, out);
}